// round 16
// baseline (speedup 1.0000x reference)
#include <cuda_runtime.h>
#include <cuda_bf16.h>
#include <cstdint>
#include <math.h>

#define NROWS 102400      // BS * N_AGENTS
#define NBATCH 2048
#define QSIZE (NROWS * 8)

// ---------------- static scratch ----------------
__device__ float          g_gi[NROWS * 384];
__device__ __nv_bfloat16  g_wgs[128 * 256];      // w_gcn split
__device__ __nv_bfloat16  g_wihs[384 * 256];     // w_ih split
__device__ __nv_bfloat16  g_whhs[384 * 256];     // w_hh split
__device__ __nv_bfloat16  g_adjcs[64 * 136];     // adj split [64][hi64|lo64|pad8]

// ---------------- tile geometry ----------------
#define LDS_K 264     // K=256 hi|lo + 8 pad
#define LDS_A 136     // adjC row stride
#define BM 64
#define A_TILE (BM * LDS_K)
#define B_TILE (128 * LDS_K)
#define GEMM_SMEM ((A_TILE + B_TILE) * 2)  // 101376 B

// fused GCN smem (bf16 element offsets)
#define GX_OFF 0
#define GW_OFF (128 * LDS_K)
#define GY_OFF (2 * 128 * LDS_K)
#define GA_OFF (3 * 128 * LDS_K)
#define GCN_SMEM ((GA_OFF + 64 * LDS_A) * 2)   // 220160 B

// ---------------- cp.async helpers ----------------
__device__ __forceinline__ uint32_t smem_u32(const void* p) {
    uint32_t a;
    asm("{ .reg .u64 t; cvta.to.shared.u64 t, %1; cvt.u32.u64 %0, t; }" : "=r"(a) : "l"(p));
    return a;
}
#define CP16(dst_u32, src_ptr) \
    asm volatile("cp.async.cg.shared.global [%0], [%1], 16;" :: "r"(dst_u32), "l"(src_ptr))
#define CP_COMMIT()  asm volatile("cp.async.commit_group;" ::: "memory")
#define CP_WAIT0()   asm volatile("cp.async.wait_group 0;" ::: "memory")

template <int ROWS, int NTHR>
__device__ __forceinline__ void fill_bf16_ca(__nv_bfloat16* S, const __nv_bfloat16* G,
                                             int tid) {
    uint32_t sb = smem_u32(S);
    const uint4* g = reinterpret_cast<const uint4*>(G);
    for (int i = tid; i < ROWS * 32; i += NTHR) {
        int r = i >> 5, c = i & 31;
        CP16(sb + (r * LDS_K + c * 8) * 2, g + r * 32 + c);
    }
}
__device__ __forceinline__ void split_store(__nv_bfloat16* S, int r, int c, float4 v) {
    __nv_bfloat16 h0 = __float2bfloat16(v.x), h1 = __float2bfloat16(v.y);
    __nv_bfloat16 h2 = __float2bfloat16(v.z), h3 = __float2bfloat16(v.w);
    __nv_bfloat162 H0{h0, h1}, H1{h2, h3};
    __nv_bfloat162 L0{__float2bfloat16(v.x - __bfloat162float(h0)),
                      __float2bfloat16(v.y - __bfloat162float(h1))};
    __nv_bfloat162 L1{__float2bfloat16(v.z - __bfloat162float(h2)),
                      __float2bfloat16(v.w - __bfloat162float(h3))};
    __nv_bfloat16* hp = &S[r * LDS_K + c * 4];
    __nv_bfloat16* lp = &S[r * LDS_K + 128 + c * 4];
    *reinterpret_cast<__nv_bfloat162*>(hp)     = H0;
    *reinterpret_cast<__nv_bfloat162*>(hp + 2) = H1;
    *reinterpret_cast<__nv_bfloat162*>(lp)     = L0;
    *reinterpret_cast<__nv_bfloat162*>(lp + 2) = L1;
}
__device__ __forceinline__ void fill_f32split(__nv_bfloat16* S, const float* G, int tid) {
    const float4* g = reinterpret_cast<const float4*>(G);
    for (int i = tid; i < BM * 32; i += 256) {
        int r = i >> 5, c = i & 31;
        split_store(S, r, c, g[r * 32 + c]);
    }
}

// ---------------------------------------------------------------------------
// Compensated MMA over [hi|lo] K=256 tiles, stride LDS_K (proven).
// ---------------------------------------------------------------------------
template <int NT>
__device__ __forceinline__ void mma_comp(const __nv_bfloat16* As, const __nv_bfloat16* Bs,
                                         int mrow0, int ncol0, int grp, int tig,
                                         float (&acc)[2][NT][4]) {
#pragma unroll
    for (int mt = 0; mt < 2; mt++)
#pragma unroll
        for (int nt = 0; nt < NT; nt++)
#pragma unroll
            for (int q = 0; q < 4; q++) acc[mt][nt][q] = 0.f;

    const int segA[3] = {0, 128, 0};
    const int segB[3] = {0, 0, 128};
#pragma unroll
    for (int seg = 0; seg < 3; seg++) {
#pragma unroll
        for (int ks = 0; ks < 8; ks++) {
            int ka = segA[seg] + ks * 16;
            int kb = segB[seg] + ks * 16;
            uint32_t afr[2][4];
#pragma unroll
            for (int mt = 0; mt < 2; mt++) {
                int r = mrow0 + mt * 16 + grp;
                const uint32_t* p0 = reinterpret_cast<const uint32_t*>(&As[r * LDS_K + ka + tig * 2]);
                const uint32_t* p1 = reinterpret_cast<const uint32_t*>(&As[(r + 8) * LDS_K + ka + tig * 2]);
                afr[mt][0] = p0[0];
                afr[mt][1] = p1[0];
                afr[mt][2] = p0[4];
                afr[mt][3] = p1[4];
            }
            uint32_t bfr[NT][2];
#pragma unroll
            for (int nt = 0; nt < NT; nt++) {
                int n = ncol0 + nt * 8 + grp;
                const uint32_t* q = reinterpret_cast<const uint32_t*>(&Bs[n * LDS_K + kb + tig * 2]);
                bfr[nt][0] = q[0];
                bfr[nt][1] = q[4];
            }
#pragma unroll
            for (int mt = 0; mt < 2; mt++)
#pragma unroll
                for (int nt = 0; nt < NT; nt++)
                    asm volatile(
                        "mma.sync.aligned.m16n8k16.row.col.f32.bf16.bf16.f32 "
                        "{%0,%1,%2,%3}, {%4,%5,%6,%7}, {%8,%9}, {%0,%1,%2,%3};"
                        : "+f"(acc[mt][nt][0]), "+f"(acc[mt][nt][1]),
                          "+f"(acc[mt][nt][2]), "+f"(acc[mt][nt][3])
                        : "r"(afr[mt][0]), "r"(afr[mt][1]), "r"(afr[mt][2]), "r"(afr[mt][3]),
                          "r"(bfr[nt][0]), "r"(bfr[nt][1]));
        }
    }
}

// Generalized: separate A/B strides and per-segment k-offsets (adj stage).
template <int LDA, int LDB, int KS, int NT>
__device__ __forceinline__ void mma_comp2(const __nv_bfloat16* As, const __nv_bfloat16* Bs,
                                          const int (&aoff)[3], const int (&boff)[3],
                                          int mrow0, int ncol0, int grp, int tig,
                                          float (&acc)[2][NT][4]) {
#pragma unroll
    for (int mt = 0; mt < 2; mt++)
#pragma unroll
        for (int nt = 0; nt < NT; nt++)
#pragma unroll
            for (int q = 0; q < 4; q++) acc[mt][nt][q] = 0.f;

#pragma unroll
    for (int seg = 0; seg < 3; seg++) {
#pragma unroll
        for (int ks = 0; ks < KS; ks++) {
            int ka = aoff[seg] + ks * 16;
            int kb = boff[seg] + ks * 16;
            uint32_t afr[2][4];
#pragma unroll
            for (int mt = 0; mt < 2; mt++) {
                int r = mrow0 + mt * 16 + grp;
                const uint32_t* p0 = reinterpret_cast<const uint32_t*>(&As[r * LDA + ka + tig * 2]);
                const uint32_t* p1 = reinterpret_cast<const uint32_t*>(&As[(r + 8) * LDA + ka + tig * 2]);
                afr[mt][0] = p0[0];
                afr[mt][1] = p1[0];
                afr[mt][2] = p0[4];
                afr[mt][3] = p1[4];
            }
            uint32_t bfr[NT][2];
#pragma unroll
            for (int nt = 0; nt < NT; nt++) {
                int n = ncol0 + nt * 8 + grp;
                const uint32_t* q = reinterpret_cast<const uint32_t*>(&Bs[n * LDB + kb + tig * 2]);
                bfr[nt][0] = q[0];
                bfr[nt][1] = q[4];
            }
#pragma unroll
            for (int mt = 0; mt < 2; mt++)
#pragma unroll
                for (int nt = 0; nt < NT; nt++)
                    asm volatile(
                        "mma.sync.aligned.m16n8k16.row.col.f32.bf16.bf16.f32 "
                        "{%0,%1,%2,%3}, {%4,%5,%6,%7}, {%8,%9}, {%0,%1,%2,%3};"
                        : "+f"(acc[mt][nt][0]), "+f"(acc[mt][nt][1]),
                          "+f"(acc[mt][nt][2]), "+f"(acc[mt][nt][3])
                        : "r"(afr[mt][0]), "r"(afr[mt][1]), "r"(afr[mt][2]), "r"(afr[mt][3]),
                          "r"(bfr[nt][0]), "r"(bfr[nt][1]));
        }
    }
}

// ---------------------------------------------------------------------------
// FUSED GCN + gi GEMM. One CTA = 2 samples (rows 0..49, 64..113 in Xs; pads 0).
// 3 passes of X = relu(adj @ (X @ Wg^T) + b), all tensor-core, then
// gi = X @ w_ih^T + b_ih from the smem-resident X. gi-phase fills: chunks 0,1
// prefetched concurrently into the two dead buffers (Ws, Yt), fully waited
// before use; chunks 0,1 then run with no intervening barriers; chunk 2
// refills Ws serialized (R13-proven discipline).
// 512 threads, 1 CTA/SM, grid = NBATCH/2.
// ---------------------------------------------------------------------------
__global__ void __launch_bounds__(512, 1)
gcn_fused(const float* __restrict__ inputs, const __nv_bfloat16* __restrict__ Wg,
          const __nv_bfloat16* __restrict__ wihs, const __nv_bfloat16* __restrict__ adjcs,
          const float* __restrict__ b_gcn, const float* __restrict__ b_ih,
          float* __restrict__ gi) {
    extern __shared__ __nv_bfloat16 sm[];
    __nv_bfloat16* Xs   = sm + GX_OFF;   // [128][264]
    __nv_bfloat16* Ws   = sm + GW_OFF;   // [128][264]
    __nv_bfloat16* Yt   = sm + GY_OFF;   // [128][264]
    __nv_bfloat16* adjC = sm + GA_OFF;   // [64][136]

    int tid = threadIdx.x;
    int wid = tid >> 5, lane = tid & 31;
    int grp = lane >> 2, tig = lane & 3;
    int g_mrow0 = (wid & 3) * 32;
    int g_ncol0 = (wid >> 2) * 32;
    int a_s     = wid >> 3;
    int aw      = wid & 7;
    int a_mrow0 = (aw & 1) * 32;
    int a_ncol0 = (aw >> 1) * 32;

    size_t m0g = (size_t)blockIdx.x * 100;

    // --- initial fills ---
    fill_bf16_ca<128, 512>(Ws, Wg, tid);
    {   // adjC: 1088 uint4
        uint32_t sb = smem_u32(adjC);
        const uint4* g = reinterpret_cast<const uint4*>(adjcs);
        for (int i = tid; i < 1088; i += 512) CP16(sb + i * 16, g + i);
    }
    {   // X rows: global g (0..99) -> local (g/50)*64 + g%50
        const float4* g4 = reinterpret_cast<const float4*>(inputs + m0g * 128);
        for (int i = tid; i < 100 * 32; i += 512) {
            int g = i >> 5, c = i & 31;
            int s = (g >= 50);
            split_store(Xs, s * 64 + (g - s * 50), c, g4[g * 32 + c]);
        }
        for (int i = tid; i < 28 * 132; i += 512) {
            int r = i / 132, c = i - (i / 132) * 132;
            int rr = (r < 14) ? (50 + r) : (114 + r - 14);
            reinterpret_cast<uint32_t*>(&Xs[rr * LDS_K])[c] = 0;
        }
    }
    float bb[4][2];
#pragma unroll
    for (int nt = 0; nt < 4; nt++) {
        int d = a_ncol0 + nt * 8 + tig * 2;
        bb[nt][0] = b_gcn[d];
        bb[nt][1] = b_gcn[d + 1];
    }
    const int aoffs[3] = {0, 64, 0};
    const int boffs[3] = {a_s * 64, a_s * 64, 128 + a_s * 64};

    CP_COMMIT();
    CP_WAIT0();
    __syncthreads();

    for (int p = 0; p < 3; p++) {
        // phase1: Yt[d][j] = sum_k W[d,k] X[j,k]
        {
            float acc[2][4][4];
            mma_comp<4>(Ws, Xs, g_mrow0, g_ncol0, grp, tig, acc);
#pragma unroll
            for (int mt = 0; mt < 2; mt++) {
#pragma unroll
                for (int half = 0; half < 2; half++) {
                    int d = g_mrow0 + mt * 16 + grp + half * 8;
                    __nv_bfloat16* yrow = Yt + d * LDS_K;
#pragma unroll
                    for (int nt = 0; nt < 4; nt++) {
                        int j = g_ncol0 + nt * 8 + tig * 2;
                        float v0 = acc[mt][nt][half * 2 + 0];
                        float v1 = acc[mt][nt][half * 2 + 1];
                        __nv_bfloat16 h0 = __float2bfloat16(v0);
                        __nv_bfloat16 h1 = __float2bfloat16(v1);
                        *reinterpret_cast<__nv_bfloat162*>(yrow + j) = __nv_bfloat162{h0, h1};
                        *reinterpret_cast<__nv_bfloat162*>(yrow + 128 + j) =
                            __nv_bfloat162{__float2bfloat16(v0 - __bfloat162float(h0)),
                                           __float2bfloat16(v1 - __bfloat162float(h1))};
                    }
                }
            }
        }
        __syncthreads();

        // phase2: X' = relu(adj @ Y + b) -> back into Xs (all 3 passes)
        {
            float acc[2][4][4];
            mma_comp2<LDS_A, LDS_K, 4, 4>(adjC, Yt, aoffs, boffs,
                                          a_mrow0, a_ncol0, grp, tig, acc);
#pragma unroll
            for (int mt = 0; mt < 2; mt++) {
#pragma unroll
                for (int half = 0; half < 2; half++) {
                    int i_loc = a_mrow0 + mt * 16 + grp + half * 8;
                    if (i_loc < 50) {
                        __nv_bfloat16* xrow = Xs + (a_s * 64 + i_loc) * LDS_K;
#pragma unroll
                        for (int nt = 0; nt < 4; nt++) {
                            int d = a_ncol0 + nt * 8 + tig * 2;
                            float v0 = fmaxf(acc[mt][nt][half * 2 + 0] + bb[nt][0], 0.f);
                            float v1 = fmaxf(acc[mt][nt][half * 2 + 1] + bb[nt][1], 0.f);
                            __nv_bfloat16 h0 = __float2bfloat16(v0);
                            __nv_bfloat16 h1 = __float2bfloat16(v1);
                            *reinterpret_cast<__nv_bfloat162*>(xrow + d) = __nv_bfloat162{h0, h1};
                            *reinterpret_cast<__nv_bfloat162*>(xrow + 128 + d) =
                                __nv_bfloat162{__float2bfloat16(v0 - __bfloat162float(h0)),
                                               __float2bfloat16(v1 - __bfloat162float(h1))};
                        }
                    }
                }
            }
        }
        __syncthreads();
    }

    // ---- gi = X @ w_ih^T + b_ih ----
    // Ws dead (last read: pass-3 phase-1 mma); Yt dead (last read: pass-3
    // phase-2 mma); both ordered by the final pass __syncthreads above.
    fill_bf16_ca<128, 512>(Ws, wihs, tid);                   // chunk 0
    CP_COMMIT();
    fill_bf16_ca<128, 512>(Yt, wihs + 128 * 256, tid);       // chunk 1
    CP_COMMIT();
    CP_WAIT0();          // both chunks fully resident
    __syncthreads();

    for (int j = 0; j < 3; j++) {
        if (j == 2) {
            __syncthreads();   // all chunk-0 reads of Ws complete (program order)
            fill_bf16_ca<128, 512>(Ws, wihs + (size_t)2 * 128 * 256, tid);
            CP_COMMIT();
            CP_WAIT0();
            __syncthreads();
        }
        const __nv_bfloat16* Wb = (j == 1) ? Yt : Ws;

        float acc[2][4][4];
        mma_comp<4>(Xs, Wb, g_mrow0, g_ncol0, grp, tig, acc);

#pragma unroll
        for (int mt = 0; mt < 2; mt++) {
#pragma unroll
            for (int half = 0; half < 2; half++) {
                int r = g_mrow0 + mt * 16 + grp + half * 8;
                int rl = r & 63;
                if (rl < 50) {
                    size_t grow = m0g + (size_t)(r >> 6) * 50 + rl;
                    float* girow = gi + grow * 384 + j * 128;
#pragma unroll
                    for (int nt = 0; nt < 4; nt++) {
                        int c = g_ncol0 + nt * 8 + tig * 2;
                        float2 v = {acc[mt][nt][half * 2 + 0] + b_ih[j * 128 + c],
                                    acc[mt][nt][half * 2 + 1] + b_ih[j * 128 + c + 1]};
                        *reinterpret_cast<float2*>(girow + c) = v;
                    }
                }
            }
        }
    }
}

// ---------------------------------------------------------------------------
// Fused gh GEMM + GRU gates + fc2. r,z gates in registers; h staged to smem
// (reusing the As region after its final mma read) for the fc2 dot.
// (R13-proven, byte-identical)
// ---------------------------------------------------------------------------
__global__ void __launch_bounds__(256, 2)
gemm_gru(const float* __restrict__ hidden, const __nv_bfloat16* __restrict__ W,
         const float* __restrict__ gi, const float* __restrict__ b_hh,
         const float* __restrict__ w_fc2, const float* __restrict__ b_fc2,
         float* __restrict__ h_out, float* __restrict__ q_out) {
    extern __shared__ __nv_bfloat16 sm[];
    __nv_bfloat16* As = sm;
    __nv_bfloat16* Bs = sm + A_TILE;
    float* Hs = reinterpret_cast<float*>(sm);            // [64][132], overlaps As
    float* Wf = reinterpret_cast<float*>(sm + A_TILE);   // [8][132], overlaps Bs

    int tid = threadIdx.x;
    int wid = tid >> 5, lane = tid & 31;
    int grp = lane >> 2, tig = lane & 3;
    int mrow0 = (wid & 1) * 32;
    int ncol0 = (wid >> 1) * 32;
    size_t m0 = (size_t)blockIdx.x * BM;

    fill_bf16_ca<128, 256>(Bs, W, tid);
    fill_f32split(As, hidden + m0 * 128, tid);
    CP_COMMIT();
    CP_WAIT0();
    __syncthreads();

    float rreg[2][4][4];
    float zreg[2][4][4];

    for (int j = 0; j < 3; j++) {
        float acc[2][4][4];
        mma_comp<4>(As, Bs, mrow0, ncol0, grp, tig, acc);

        if (j == 2) __syncthreads();   // all mma reads of As done before Hs writes

#pragma unroll
        for (int mt = 0; mt < 2; mt++) {
#pragma unroll
            for (int nt = 0; nt < 4; nt++) {
                size_t row0 = m0 + mrow0 + mt * 16 + grp;
                int c = ncol0 + nt * 8 + tig * 2;
                float bb0 = b_hh[j * 128 + c], bb1 = b_hh[j * 128 + c + 1];
                float2 gi0 = *reinterpret_cast<const float2*>(&gi[row0 * 384 + j * 128 + c]);
                float2 gi1 = *reinterpret_cast<const float2*>(&gi[(row0 + 8) * 384 + j * 128 + c]);
                float gh00 = acc[mt][nt][0] + bb0, gh01 = acc[mt][nt][1] + bb1;
                float gh10 = acc[mt][nt][2] + bb0, gh11 = acc[mt][nt][3] + bb1;
                if (j == 0) {
                    rreg[mt][nt][0] = 1.f / (1.f + expf(-(gi0.x + gh00)));
                    rreg[mt][nt][1] = 1.f / (1.f + expf(-(gi0.y + gh01)));
                    rreg[mt][nt][2] = 1.f / (1.f + expf(-(gi1.x + gh10)));
                    rreg[mt][nt][3] = 1.f / (1.f + expf(-(gi1.y + gh11)));
                } else if (j == 1) {
                    zreg[mt][nt][0] = 1.f / (1.f + expf(-(gi0.x + gh00)));
                    zreg[mt][nt][1] = 1.f / (1.f + expf(-(gi0.y + gh01)));
                    zreg[mt][nt][2] = 1.f / (1.f + expf(-(gi1.x + gh10)));
                    zreg[mt][nt][3] = 1.f / (1.f + expf(-(gi1.y + gh11)));
                } else {
                    float n00 = tanhf(gi0.x + rreg[mt][nt][0] * gh00);
                    float n01 = tanhf(gi0.y + rreg[mt][nt][1] * gh01);
                    float n10 = tanhf(gi1.x + rreg[mt][nt][2] * gh10);
                    float n11 = tanhf(gi1.y + rreg[mt][nt][3] * gh11);
                    float2 hv0 = *reinterpret_cast<const float2*>(&hidden[row0 * 128 + c]);
                    float2 hv1 = *reinterpret_cast<const float2*>(&hidden[(row0 + 8) * 128 + c]);
                    float z00 = zreg[mt][nt][0], z01 = zreg[mt][nt][1];
                    float z10 = zreg[mt][nt][2], z11 = zreg[mt][nt][3];
                    float2 o0 = {(1.f - z00) * n00 + z00 * hv0.x,
                                 (1.f - z01) * n01 + z01 * hv0.y};
                    float2 o1 = {(1.f - z10) * n10 + z10 * hv1.x,
                                 (1.f - z11) * n11 + z11 * hv1.y};
                    *reinterpret_cast<float2*>(&h_out[row0 * 128 + c]) = o0;
                    *reinterpret_cast<float2*>(&h_out[(row0 + 8) * 128 + c]) = o1;
                    int lr = mrow0 + mt * 16 + grp;
                    *reinterpret_cast<float2*>(&Hs[lr * 132 + c])       = o0;
                    *reinterpret_cast<float2*>(&Hs[(lr + 8) * 132 + c]) = o1;
                }
            }
        }
        if (j < 2) {
            __syncthreads();
            fill_bf16_ca<128, 256>(Bs, W + (size_t)(j + 1) * 128 * 256, tid);
            CP_COMMIT();
            CP_WAIT0();
            __syncthreads();
        }
    }
    __syncthreads();

    // ---- fc2: q = Hs @ w_fc2^T + b ----
    for (int i = tid; i < 8 * 32; i += 256) {   // Wf fill (float4 units)
        int r = i >> 5, c4 = (i & 31) << 2;
        *reinterpret_cast<float4*>(&Wf[r * 132 + c4]) =
            *reinterpret_cast<const float4*>(&w_fc2[r * 128 + c4]);
    }
    __syncthreads();
#pragma unroll
    for (int o = tid; o < 512; o += 256) {
        int rl = o >> 3, a = o & 7;
        const float* hr = &Hs[rl * 132];
        const float* wr = &Wf[a * 132];
        float acc = 0.f;
#pragma unroll
        for (int k = 0; k < 128; k++) acc += hr[k] * wr[k];
        q_out[(m0 + rl) * 8 + a] = acc + b_fc2[a];
    }
}

// ---------------------------------------------------------------------------
// One-shot setup: weight hi|lo splits + adj split tile. 113 blocks x 256.
// ---------------------------------------------------------------------------
__device__ __forceinline__ void cvt_one(const float* in, __nv_bfloat16* outS, int i) {
    float4 v = reinterpret_cast<const float4*>(in)[i];
    int row = i >> 5, c4 = (i & 31) << 2;
    __nv_bfloat16 h0 = __float2bfloat16(v.x), h1 = __float2bfloat16(v.y);
    __nv_bfloat16 h2 = __float2bfloat16(v.z), h3 = __float2bfloat16(v.w);
    __nv_bfloat16* base = outS + (size_t)row * 256;
    *reinterpret_cast<__nv_bfloat162*>(base + c4)     = __nv_bfloat162{h0, h1};
    *reinterpret_cast<__nv_bfloat162*>(base + c4 + 2) = __nv_bfloat162{h2, h3};
    *reinterpret_cast<__nv_bfloat162*>(base + 128 + c4) =
        __nv_bfloat162{__float2bfloat16(v.x - __bfloat162float(h0)),
                       __float2bfloat16(v.y - __bfloat162float(h1))};
    *reinterpret_cast<__nv_bfloat162*>(base + 128 + c4 + 2) =
        __nv_bfloat162{__float2bfloat16(v.z - __bfloat162float(h2)),
                       __float2bfloat16(v.w - __bfloat162float(h3))};
}

__global__ void setup_all(const float* __restrict__ w_gcn, const float* __restrict__ w_ih,
                          const float* __restrict__ w_hh, const float* __restrict__ adj,
                          __nv_bfloat16* __restrict__ wgs, __nv_bfloat16* __restrict__ wihs,
                          __nv_bfloat16* __restrict__ whhs, __nv_bfloat16* __restrict__ adjcs) {
    int b = blockIdx.x, tid = threadIdx.x;
    if (b < 16) {
        cvt_one(w_gcn, wgs, b * 256 + tid);
    } else if (b < 64) {
        cvt_one(w_ih, wihs, (b - 16) * 256 + tid);
    } else if (b < 112) {
        cvt_one(w_hh, whhs, (b - 64) * 256 + tid);
    } else {
        for (int idx = tid; idx < 64 * 136; idx += 256) {
            int r = idx / 136, k = idx - (idx / 136) * 136;
            int j = (k < 64) ? k : k - 64;
            float v = (k < 128 && r < 50 && j < 50) ? adj[r * 50 + j] : 0.f;
            __nv_bfloat16 h = __float2bfloat16(v);
            adjcs[idx] = (k < 64) ? h : __float2bfloat16(v - __bfloat162float(h));
        }
    }
}

// ---------------------------------------------------------------------------
extern "C" void kernel_launch(void* const* d_in, const int* in_sizes, int n_in,
                              void* d_out, int out_size) {
    const float* inputs   = (const float*)d_in[0];
    const float* hidden   = (const float*)d_in[1];
    const float* norm_adj = (const float*)d_in[2];
    const float* w_gcn    = (const float*)d_in[3];
    const float* b_gcn    = (const float*)d_in[4];
    const float* w_ih     = (const float*)d_in[5];
    const float* b_ih     = (const float*)d_in[6];
    const float* w_hh     = (const float*)d_in[7];
    const float* b_hh     = (const float*)d_in[8];
    const float* w_fc2    = (const float*)d_in[9];
    const float* b_fc2    = (const float*)d_in[10];

    float* out = (float*)d_out;
    float* q_out = out;               // (102400, 8)
    float* h_out = out + QSIZE;       // (102400, 128)

    float* gi;
    __nv_bfloat16 *wgs, *wihs, *whhs, *adjcs;
    cudaGetSymbolAddress((void**)&gi, g_gi);
    cudaGetSymbolAddress((void**)&wgs, g_wgs);
    cudaGetSymbolAddress((void**)&wihs, g_wihs);
    cudaGetSymbolAddress((void**)&whhs, g_whhs);
    cudaGetSymbolAddress((void**)&adjcs, g_adjcs);

    cudaFuncSetAttribute(gcn_fused, cudaFuncAttributeMaxDynamicSharedMemorySize, GCN_SMEM);
    cudaFuncSetAttribute(gemm_gru,  cudaFuncAttributeMaxDynamicSharedMemorySize, GEMM_SMEM);

    setup_all<<<113, 256>>>(w_gcn, w_ih, w_hh, norm_adj, wgs, wihs, whhs, adjcs);

    // Fused 3-pass GCN + gi GEMM
    gcn_fused<<<NBATCH / 2, 512, GCN_SMEM>>>(inputs, wgs, wihs, adjcs, b_gcn, b_ih, gi);

    // gh GEMM + GRU + fc2
    gemm_gru<<<NROWS / BM, 256, GEMM_SMEM>>>(hidden, whhs, gi, b_hh, w_fc2, b_fc2,
                                             h_out, q_out);
}

// round 17
// speedup vs baseline: 1.0817x; 1.0817x over previous
#include <cuda_runtime.h>
#include <cuda_bf16.h>
#include <cstdint>
#include <math.h>

#define NROWS 102400      // BS * N_AGENTS
#define NBATCH 2048
#define QSIZE (NROWS * 8)

// ---------------- static scratch ----------------
__device__ float          g_gi[NROWS * 384];
__device__ __nv_bfloat16  g_wgs[128 * 256];      // w_gcn split
__device__ __nv_bfloat16  g_wihs[384 * 256];     // w_ih split
__device__ __nv_bfloat16  g_whhs[384 * 256];     // w_hh split
__device__ __nv_bfloat16  g_adjcs[64 * 136];     // adj split [64][hi64|lo64|pad8]

// ---------------- tile geometry ----------------
#define LDS_K 264     // K=256 hi|lo + 8 pad
#define LDS_A 136     // adjC row stride
#define BM 64
#define A_TILE (BM * LDS_K)
#define B_TILE (128 * LDS_K)
#define GEMM_SMEM ((A_TILE + B_TILE) * 2)  // 101376 B

// fused GCN smem (bf16 element offsets)
#define GX_OFF 0
#define GW_OFF (128 * LDS_K)
#define GY_OFF (2 * 128 * LDS_K)
#define GA_OFF (3 * 128 * LDS_K)
#define GCN_SMEM ((GA_OFF + 64 * LDS_A) * 2)   // 220160 B

// ---------------- cp.async helpers ----------------
__device__ __forceinline__ uint32_t smem_u32(const void* p) {
    uint32_t a;
    asm("{ .reg .u64 t; cvta.to.shared.u64 t, %1; cvt.u32.u64 %0, t; }" : "=r"(a) : "l"(p));
    return a;
}
#define CP16(dst_u32, src_ptr) \
    asm volatile("cp.async.cg.shared.global [%0], [%1], 16;" :: "r"(dst_u32), "l"(src_ptr))
#define CP_COMMIT()  asm volatile("cp.async.commit_group;" ::: "memory")
#define CP_WAIT0()   asm volatile("cp.async.wait_group 0;" ::: "memory")

template <int ROWS, int NTHR>
__device__ __forceinline__ void fill_bf16_ca(__nv_bfloat16* S, const __nv_bfloat16* G,
                                             int tid) {
    uint32_t sb = smem_u32(S);
    const uint4* g = reinterpret_cast<const uint4*>(G);
    for (int i = tid; i < ROWS * 32; i += NTHR) {
        int r = i >> 5, c = i & 31;
        CP16(sb + (r * LDS_K + c * 8) * 2, g + r * 32 + c);
    }
}
__device__ __forceinline__ void split_store(__nv_bfloat16* S, int r, int c, float4 v) {
    __nv_bfloat16 h0 = __float2bfloat16(v.x), h1 = __float2bfloat16(v.y);
    __nv_bfloat16 h2 = __float2bfloat16(v.z), h3 = __float2bfloat16(v.w);
    __nv_bfloat162 H0{h0, h1}, H1{h2, h3};
    __nv_bfloat162 L0{__float2bfloat16(v.x - __bfloat162float(h0)),
                      __float2bfloat16(v.y - __bfloat162float(h1))};
    __nv_bfloat162 L1{__float2bfloat16(v.z - __bfloat162float(h2)),
                      __float2bfloat16(v.w - __bfloat162float(h3))};
    __nv_bfloat16* hp = &S[r * LDS_K + c * 4];
    __nv_bfloat16* lp = &S[r * LDS_K + 128 + c * 4];
    *reinterpret_cast<__nv_bfloat162*>(hp)     = H0;
    *reinterpret_cast<__nv_bfloat162*>(hp + 2) = H1;
    *reinterpret_cast<__nv_bfloat162*>(lp)     = L0;
    *reinterpret_cast<__nv_bfloat162*>(lp + 2) = L1;
}
__device__ __forceinline__ void fill_f32split(__nv_bfloat16* S, const float* G, int tid) {
    const float4* g = reinterpret_cast<const float4*>(G);
    for (int i = tid; i < BM * 32; i += 256) {
        int r = i >> 5, c = i & 31;
        split_store(S, r, c, g[r * 32 + c]);
    }
}

// ---------------------------------------------------------------------------
// Compensated MMA over [hi|lo] K=256 tiles, stride LDS_K (proven).
// ---------------------------------------------------------------------------
template <int NT>
__device__ __forceinline__ void mma_comp(const __nv_bfloat16* As, const __nv_bfloat16* Bs,
                                         int mrow0, int ncol0, int grp, int tig,
                                         float (&acc)[2][NT][4]) {
#pragma unroll
    for (int mt = 0; mt < 2; mt++)
#pragma unroll
        for (int nt = 0; nt < NT; nt++)
#pragma unroll
            for (int q = 0; q < 4; q++) acc[mt][nt][q] = 0.f;

    const int segA[3] = {0, 128, 0};
    const int segB[3] = {0, 0, 128};
#pragma unroll
    for (int seg = 0; seg < 3; seg++) {
#pragma unroll
        for (int ks = 0; ks < 8; ks++) {
            int ka = segA[seg] + ks * 16;
            int kb = segB[seg] + ks * 16;
            uint32_t afr[2][4];
#pragma unroll
            for (int mt = 0; mt < 2; mt++) {
                int r = mrow0 + mt * 16 + grp;
                const uint32_t* p0 = reinterpret_cast<const uint32_t*>(&As[r * LDS_K + ka + tig * 2]);
                const uint32_t* p1 = reinterpret_cast<const uint32_t*>(&As[(r + 8) * LDS_K + ka + tig * 2]);
                afr[mt][0] = p0[0];
                afr[mt][1] = p1[0];
                afr[mt][2] = p0[4];
                afr[mt][3] = p1[4];
            }
            uint32_t bfr[NT][2];
#pragma unroll
            for (int nt = 0; nt < NT; nt++) {
                int n = ncol0 + nt * 8 + grp;
                const uint32_t* q = reinterpret_cast<const uint32_t*>(&Bs[n * LDS_K + kb + tig * 2]);
                bfr[nt][0] = q[0];
                bfr[nt][1] = q[4];
            }
#pragma unroll
            for (int mt = 0; mt < 2; mt++)
#pragma unroll
                for (int nt = 0; nt < NT; nt++)
                    asm volatile(
                        "mma.sync.aligned.m16n8k16.row.col.f32.bf16.bf16.f32 "
                        "{%0,%1,%2,%3}, {%4,%5,%6,%7}, {%8,%9}, {%0,%1,%2,%3};"
                        : "+f"(acc[mt][nt][0]), "+f"(acc[mt][nt][1]),
                          "+f"(acc[mt][nt][2]), "+f"(acc[mt][nt][3])
                        : "r"(afr[mt][0]), "r"(afr[mt][1]), "r"(afr[mt][2]), "r"(afr[mt][3]),
                          "r"(bfr[nt][0]), "r"(bfr[nt][1]));
        }
    }
}

// Generalized: separate A/B strides and per-segment k-offsets (adj stage).
template <int LDA, int LDB, int KS, int NT>
__device__ __forceinline__ void mma_comp2(const __nv_bfloat16* As, const __nv_bfloat16* Bs,
                                          const int (&aoff)[3], const int (&boff)[3],
                                          int mrow0, int ncol0, int grp, int tig,
                                          float (&acc)[2][NT][4]) {
#pragma unroll
    for (int mt = 0; mt < 2; mt++)
#pragma unroll
        for (int nt = 0; nt < NT; nt++)
#pragma unroll
            for (int q = 0; q < 4; q++) acc[mt][nt][q] = 0.f;

#pragma unroll
    for (int seg = 0; seg < 3; seg++) {
#pragma unroll
        for (int ks = 0; ks < KS; ks++) {
            int ka = aoff[seg] + ks * 16;
            int kb = boff[seg] + ks * 16;
            uint32_t afr[2][4];
#pragma unroll
            for (int mt = 0; mt < 2; mt++) {
                int r = mrow0 + mt * 16 + grp;
                const uint32_t* p0 = reinterpret_cast<const uint32_t*>(&As[r * LDA + ka + tig * 2]);
                const uint32_t* p1 = reinterpret_cast<const uint32_t*>(&As[(r + 8) * LDA + ka + tig * 2]);
                afr[mt][0] = p0[0];
                afr[mt][1] = p1[0];
                afr[mt][2] = p0[4];
                afr[mt][3] = p1[4];
            }
            uint32_t bfr[NT][2];
#pragma unroll
            for (int nt = 0; nt < NT; nt++) {
                int n = ncol0 + nt * 8 + grp;
                const uint32_t* q = reinterpret_cast<const uint32_t*>(&Bs[n * LDB + kb + tig * 2]);
                bfr[nt][0] = q[0];
                bfr[nt][1] = q[4];
            }
#pragma unroll
            for (int mt = 0; mt < 2; mt++)
#pragma unroll
                for (int nt = 0; nt < NT; nt++)
                    asm volatile(
                        "mma.sync.aligned.m16n8k16.row.col.f32.bf16.bf16.f32 "
                        "{%0,%1,%2,%3}, {%4,%5,%6,%7}, {%8,%9}, {%0,%1,%2,%3};"
                        : "+f"(acc[mt][nt][0]), "+f"(acc[mt][nt][1]),
                          "+f"(acc[mt][nt][2]), "+f"(acc[mt][nt][3])
                        : "r"(afr[mt][0]), "r"(afr[mt][1]), "r"(afr[mt][2]), "r"(afr[mt][3]),
                          "r"(bfr[nt][0]), "r"(bfr[nt][1]));
        }
    }
}

// ---------------------------------------------------------------------------
// FUSED GCN + gi GEMM, 256 threads / 8 warps with 32x64 warp tiles (NT=8)
// to cut smem-crossbar fragment traffic 25% vs the 16-warp 32x32 layout.
// One CTA = 2 samples (rows 0..49, 64..113 in Xs; pads 0); 3 passes of
// X = relu(adj @ (X @ Wg^T) + b), then gi = X @ w_ih^T + b_ih.
// gi chunks 0,1 prefetched into the dead Ws/Yt buffers (R16-proven).
// ---------------------------------------------------------------------------
__global__ void __launch_bounds__(256, 1)
gcn_fused(const float* __restrict__ inputs, const __nv_bfloat16* __restrict__ Wg,
          const __nv_bfloat16* __restrict__ wihs, const __nv_bfloat16* __restrict__ adjcs,
          const float* __restrict__ b_gcn, const float* __restrict__ b_ih,
          float* __restrict__ gi) {
    extern __shared__ __nv_bfloat16 sm[];
    __nv_bfloat16* Xs   = sm + GX_OFF;   // [128][264]
    __nv_bfloat16* Ws   = sm + GW_OFF;   // [128][264]
    __nv_bfloat16* Yt   = sm + GY_OFF;   // [128][264]
    __nv_bfloat16* adjC = sm + GA_OFF;   // [64][136]

    int tid = threadIdx.x;
    int wid = tid >> 5, lane = tid & 31;
    int grp = lane >> 2, tig = lane & 3;
    // phase1/gi warp grid: 4(m) x 2(n), warp tile 32x64 (NT=8)
    int g_mrow0 = (wid & 3) * 32;
    int g_ncol0 = (wid >> 2) * 64;
    // phase2: sample = wid>>2; within: 2(m) x 2(n), warp tile 32x64 (NT=8)
    int a_s     = wid >> 2;
    int aw      = wid & 3;
    int a_mrow0 = (aw & 1) * 32;
    int a_ncol0 = (aw >> 1) * 64;

    size_t m0g = (size_t)blockIdx.x * 100;

    // --- initial fills ---
    fill_bf16_ca<128, 256>(Ws, Wg, tid);
    {   // adjC: 1088 uint4
        uint32_t sb = smem_u32(adjC);
        const uint4* g = reinterpret_cast<const uint4*>(adjcs);
        for (int i = tid; i < 1088; i += 256) CP16(sb + i * 16, g + i);
    }
    {   // X rows: global g (0..99) -> local (g/50)*64 + g%50
        const float4* g4 = reinterpret_cast<const float4*>(inputs + m0g * 128);
        for (int i = tid; i < 100 * 32; i += 256) {
            int g = i >> 5, c = i & 31;
            int s = (g >= 50);
            split_store(Xs, s * 64 + (g - s * 50), c, g4[g * 32 + c]);
        }
        for (int i = tid; i < 28 * 132; i += 256) {
            int r = i / 132, c = i - (i / 132) * 132;
            int rr = (r < 14) ? (50 + r) : (114 + r - 14);
            reinterpret_cast<uint32_t*>(&Xs[rr * LDS_K])[c] = 0;
        }
    }
    float bb[8][2];
#pragma unroll
    for (int nt = 0; nt < 8; nt++) {
        int d = a_ncol0 + nt * 8 + tig * 2;
        bb[nt][0] = b_gcn[d];
        bb[nt][1] = b_gcn[d + 1];
    }
    const int aoffs[3] = {0, 64, 0};
    const int boffs[3] = {a_s * 64, a_s * 64, 128 + a_s * 64};

    CP_COMMIT();
    CP_WAIT0();
    __syncthreads();

    for (int p = 0; p < 3; p++) {
        // phase1: Yt[d][j] = sum_k W[d,k] X[j,k]
        {
            float acc[2][8][4];
            mma_comp<8>(Ws, Xs, g_mrow0, g_ncol0, grp, tig, acc);
#pragma unroll
            for (int mt = 0; mt < 2; mt++) {
#pragma unroll
                for (int half = 0; half < 2; half++) {
                    int d = g_mrow0 + mt * 16 + grp + half * 8;
                    __nv_bfloat16* yrow = Yt + d * LDS_K;
#pragma unroll
                    for (int nt = 0; nt < 8; nt++) {
                        int j = g_ncol0 + nt * 8 + tig * 2;
                        float v0 = acc[mt][nt][half * 2 + 0];
                        float v1 = acc[mt][nt][half * 2 + 1];
                        __nv_bfloat16 h0 = __float2bfloat16(v0);
                        __nv_bfloat16 h1 = __float2bfloat16(v1);
                        *reinterpret_cast<__nv_bfloat162*>(yrow + j) = __nv_bfloat162{h0, h1};
                        *reinterpret_cast<__nv_bfloat162*>(yrow + 128 + j) =
                            __nv_bfloat162{__float2bfloat16(v0 - __bfloat162float(h0)),
                                           __float2bfloat16(v1 - __bfloat162float(h1))};
                    }
                }
            }
        }
        __syncthreads();

        // phase2: X' = relu(adj @ Y + b) -> back into Xs
        {
            float acc[2][8][4];
            mma_comp2<LDS_A, LDS_K, 4, 8>(adjC, Yt, aoffs, boffs,
                                          a_mrow0, a_ncol0, grp, tig, acc);
#pragma unroll
            for (int mt = 0; mt < 2; mt++) {
#pragma unroll
                for (int half = 0; half < 2; half++) {
                    int i_loc = a_mrow0 + mt * 16 + grp + half * 8;
                    if (i_loc < 50) {
                        __nv_bfloat16* xrow = Xs + (a_s * 64 + i_loc) * LDS_K;
#pragma unroll
                        for (int nt = 0; nt < 8; nt++) {
                            int d = a_ncol0 + nt * 8 + tig * 2;
                            float v0 = fmaxf(acc[mt][nt][half * 2 + 0] + bb[nt][0], 0.f);
                            float v1 = fmaxf(acc[mt][nt][half * 2 + 1] + bb[nt][1], 0.f);
                            __nv_bfloat16 h0 = __float2bfloat16(v0);
                            __nv_bfloat16 h1 = __float2bfloat16(v1);
                            *reinterpret_cast<__nv_bfloat162*>(xrow + d) = __nv_bfloat162{h0, h1};
                            *reinterpret_cast<__nv_bfloat162*>(xrow + 128 + d) =
                                __nv_bfloat162{__float2bfloat16(v0 - __bfloat162float(h0)),
                                               __float2bfloat16(v1 - __bfloat162float(h1))};
                        }
                    }
                }
            }
        }
        __syncthreads();
    }

    // ---- gi = X @ w_ih^T + b_ih ----
    // Ws and Yt are dead after the final pass (ordered by the last barrier).
    fill_bf16_ca<128, 256>(Ws, wihs, tid);                   // chunk 0
    CP_COMMIT();
    fill_bf16_ca<128, 256>(Yt, wihs + 128 * 256, tid);       // chunk 1
    CP_COMMIT();
    CP_WAIT0();
    __syncthreads();

    for (int j = 0; j < 3; j++) {
        if (j == 2) {
            __syncthreads();   // all chunk-0 reads of Ws complete
            fill_bf16_ca<128, 256>(Ws, wihs + (size_t)2 * 128 * 256, tid);
            CP_COMMIT();
            CP_WAIT0();
            __syncthreads();
        }
        const __nv_bfloat16* Wb = (j == 1) ? Yt : Ws;

        float acc[2][8][4];
        mma_comp<8>(Xs, Wb, g_mrow0, g_ncol0, grp, tig, acc);

#pragma unroll
        for (int mt = 0; mt < 2; mt++) {
#pragma unroll
            for (int half = 0; half < 2; half++) {
                int r = g_mrow0 + mt * 16 + grp + half * 8;
                int rl = r & 63;
                if (rl < 50) {
                    size_t grow = m0g + (size_t)(r >> 6) * 50 + rl;
                    float* girow = gi + grow * 384 + j * 128;
#pragma unroll
                    for (int nt = 0; nt < 8; nt++) {
                        int c = g_ncol0 + nt * 8 + tig * 2;
                        float2 v = {acc[mt][nt][half * 2 + 0] + b_ih[j * 128 + c],
                                    acc[mt][nt][half * 2 + 1] + b_ih[j * 128 + c + 1]};
                        *reinterpret_cast<float2*>(girow + c) = v;
                    }
                }
            }
        }
    }
}

// ---------------------------------------------------------------------------
// Fused gh GEMM + GRU gates + fc2 (R13-proven, byte-identical).
// ---------------------------------------------------------------------------
__global__ void __launch_bounds__(256, 2)
gemm_gru(const float* __restrict__ hidden, const __nv_bfloat16* __restrict__ W,
         const float* __restrict__ gi, const float* __restrict__ b_hh,
         const float* __restrict__ w_fc2, const float* __restrict__ b_fc2,
         float* __restrict__ h_out, float* __restrict__ q_out) {
    extern __shared__ __nv_bfloat16 sm[];
    __nv_bfloat16* As = sm;
    __nv_bfloat16* Bs = sm + A_TILE;
    float* Hs = reinterpret_cast<float*>(sm);            // [64][132], overlaps As
    float* Wf = reinterpret_cast<float*>(sm + A_TILE);   // [8][132], overlaps Bs

    int tid = threadIdx.x;
    int wid = tid >> 5, lane = tid & 31;
    int grp = lane >> 2, tig = lane & 3;
    int mrow0 = (wid & 1) * 32;
    int ncol0 = (wid >> 1) * 32;
    size_t m0 = (size_t)blockIdx.x * BM;

    fill_bf16_ca<128, 256>(Bs, W, tid);
    fill_f32split(As, hidden + m0 * 128, tid);
    CP_COMMIT();
    CP_WAIT0();
    __syncthreads();

    float rreg[2][4][4];
    float zreg[2][4][4];

    for (int j = 0; j < 3; j++) {
        float acc[2][4][4];
        mma_comp<4>(As, Bs, mrow0, ncol0, grp, tig, acc);

        if (j == 2) __syncthreads();   // all mma reads of As done before Hs writes

#pragma unroll
        for (int mt = 0; mt < 2; mt++) {
#pragma unroll
            for (int nt = 0; nt < 4; nt++) {
                size_t row0 = m0 + mrow0 + mt * 16 + grp;
                int c = ncol0 + nt * 8 + tig * 2;
                float bb0 = b_hh[j * 128 + c], bb1 = b_hh[j * 128 + c + 1];
                float2 gi0 = *reinterpret_cast<const float2*>(&gi[row0 * 384 + j * 128 + c]);
                float2 gi1 = *reinterpret_cast<const float2*>(&gi[(row0 + 8) * 384 + j * 128 + c]);
                float gh00 = acc[mt][nt][0] + bb0, gh01 = acc[mt][nt][1] + bb1;
                float gh10 = acc[mt][nt][2] + bb0, gh11 = acc[mt][nt][3] + bb1;
                if (j == 0) {
                    rreg[mt][nt][0] = 1.f / (1.f + expf(-(gi0.x + gh00)));
                    rreg[mt][nt][1] = 1.f / (1.f + expf(-(gi0.y + gh01)));
                    rreg[mt][nt][2] = 1.f / (1.f + expf(-(gi1.x + gh10)));
                    rreg[mt][nt][3] = 1.f / (1.f + expf(-(gi1.y + gh11)));
                } else if (j == 1) {
                    zreg[mt][nt][0] = 1.f / (1.f + expf(-(gi0.x + gh00)));
                    zreg[mt][nt][1] = 1.f / (1.f + expf(-(gi0.y + gh01)));
                    zreg[mt][nt][2] = 1.f / (1.f + expf(-(gi1.x + gh10)));
                    zreg[mt][nt][3] = 1.f / (1.f + expf(-(gi1.y + gh11)));
                } else {
                    float n00 = tanhf(gi0.x + rreg[mt][nt][0] * gh00);
                    float n01 = tanhf(gi0.y + rreg[mt][nt][1] * gh01);
                    float n10 = tanhf(gi1.x + rreg[mt][nt][2] * gh10);
                    float n11 = tanhf(gi1.y + rreg[mt][nt][3] * gh11);
                    float2 hv0 = *reinterpret_cast<const float2*>(&hidden[row0 * 128 + c]);
                    float2 hv1 = *reinterpret_cast<const float2*>(&hidden[(row0 + 8) * 128 + c]);
                    float z00 = zreg[mt][nt][0], z01 = zreg[mt][nt][1];
                    float z10 = zreg[mt][nt][2], z11 = zreg[mt][nt][3];
                    float2 o0 = {(1.f - z00) * n00 + z00 * hv0.x,
                                 (1.f - z01) * n01 + z01 * hv0.y};
                    float2 o1 = {(1.f - z10) * n10 + z10 * hv1.x,
                                 (1.f - z11) * n11 + z11 * hv1.y};
                    *reinterpret_cast<float2*>(&h_out[row0 * 128 + c]) = o0;
                    *reinterpret_cast<float2*>(&h_out[(row0 + 8) * 128 + c]) = o1;
                    int lr = mrow0 + mt * 16 + grp;
                    *reinterpret_cast<float2*>(&Hs[lr * 132 + c])       = o0;
                    *reinterpret_cast<float2*>(&Hs[(lr + 8) * 132 + c]) = o1;
                }
            }
        }
        if (j < 2) {
            __syncthreads();
            fill_bf16_ca<128, 256>(Bs, W + (size_t)(j + 1) * 128 * 256, tid);
            CP_COMMIT();
            CP_WAIT0();
            __syncthreads();
        }
    }
    __syncthreads();

    // ---- fc2: q = Hs @ w_fc2^T + b ----
    for (int i = tid; i < 8 * 32; i += 256) {
        int r = i >> 5, c4 = (i & 31) << 2;
        *reinterpret_cast<float4*>(&Wf[r * 132 + c4]) =
            *reinterpret_cast<const float4*>(&w_fc2[r * 128 + c4]);
    }
    __syncthreads();
#pragma unroll
    for (int o = tid; o < 512; o += 256) {
        int rl = o >> 3, a = o & 7;
        const float* hr = &Hs[rl * 132];
        const float* wr = &Wf[a * 132];
        float acc = 0.f;
#pragma unroll
        for (int k = 0; k < 128; k++) acc += hr[k] * wr[k];
        q_out[(m0 + rl) * 8 + a] = acc + b_fc2[a];
    }
}

// ---------------------------------------------------------------------------
// One-shot setup: weight hi|lo splits + adj split tile. 113 blocks x 256.
// ---------------------------------------------------------------------------
__device__ __forceinline__ void cvt_one(const float* in, __nv_bfloat16* outS, int i) {
    float4 v = reinterpret_cast<const float4*>(in)[i];
    int row = i >> 5, c4 = (i & 31) << 2;
    __nv_bfloat16 h0 = __float2bfloat16(v.x), h1 = __float2bfloat16(v.y);
    __nv_bfloat16 h2 = __float2bfloat16(v.z), h3 = __float2bfloat16(v.w);
    __nv_bfloat16* base = outS + (size_t)row * 256;
    *reinterpret_cast<__nv_bfloat162*>(base + c4)     = __nv_bfloat162{h0, h1};
    *reinterpret_cast<__nv_bfloat162*>(base + c4 + 2) = __nv_bfloat162{h2, h3};
    *reinterpret_cast<__nv_bfloat162*>(base + 128 + c4) =
        __nv_bfloat162{__float2bfloat16(v.x - __bfloat162float(h0)),
                       __float2bfloat16(v.y - __bfloat162float(h1))};
    *reinterpret_cast<__nv_bfloat162*>(base + 128 + c4 + 2) =
        __nv_bfloat162{__float2bfloat16(v.z - __bfloat162float(h2)),
                       __float2bfloat16(v.w - __bfloat162float(h3))};
}

__global__ void setup_all(const float* __restrict__ w_gcn, const float* __restrict__ w_ih,
                          const float* __restrict__ w_hh, const float* __restrict__ adj,
                          __nv_bfloat16* __restrict__ wgs, __nv_bfloat16* __restrict__ wihs,
                          __nv_bfloat16* __restrict__ whhs, __nv_bfloat16* __restrict__ adjcs) {
    int b = blockIdx.x, tid = threadIdx.x;
    if (b < 16) {
        cvt_one(w_gcn, wgs, b * 256 + tid);
    } else if (b < 64) {
        cvt_one(w_ih, wihs, (b - 16) * 256 + tid);
    } else if (b < 112) {
        cvt_one(w_hh, whhs, (b - 64) * 256 + tid);
    } else {
        for (int idx = tid; idx < 64 * 136; idx += 256) {
            int r = idx / 136, k = idx - (idx / 136) * 136;
            int j = (k < 64) ? k : k - 64;
            float v = (k < 128 && r < 50 && j < 50) ? adj[r * 50 + j] : 0.f;
            __nv_bfloat16 h = __float2bfloat16(v);
            adjcs[idx] = (k < 64) ? h : __float2bfloat16(v - __bfloat162float(h));
        }
    }
}

// ---------------------------------------------------------------------------
extern "C" void kernel_launch(void* const* d_in, const int* in_sizes, int n_in,
                              void* d_out, int out_size) {
    const float* inputs   = (const float*)d_in[0];
    const float* hidden   = (const float*)d_in[1];
    const float* norm_adj = (const float*)d_in[2];
    const float* w_gcn    = (const float*)d_in[3];
    const float* b_gcn    = (const float*)d_in[4];
    const float* w_ih     = (const float*)d_in[5];
    const float* b_ih     = (const float*)d_in[6];
    const float* w_hh     = (const float*)d_in[7];
    const float* b_hh     = (const float*)d_in[8];
    const float* w_fc2    = (const float*)d_in[9];
    const float* b_fc2    = (const float*)d_in[10];

    float* out = (float*)d_out;
    float* q_out = out;               // (102400, 8)
    float* h_out = out + QSIZE;       // (102400, 128)

    float* gi;
    __nv_bfloat16 *wgs, *wihs, *whhs, *adjcs;
    cudaGetSymbolAddress((void**)&gi, g_gi);
    cudaGetSymbolAddress((void**)&wgs, g_wgs);
    cudaGetSymbolAddress((void**)&wihs, g_wihs);
    cudaGetSymbolAddress((void**)&whhs, g_whhs);
    cudaGetSymbolAddress((void**)&adjcs, g_adjcs);

    cudaFuncSetAttribute(gcn_fused, cudaFuncAttributeMaxDynamicSharedMemorySize, GCN_SMEM);
    cudaFuncSetAttribute(gemm_gru,  cudaFuncAttributeMaxDynamicSharedMemorySize, GEMM_SMEM);

    setup_all<<<113, 256>>>(w_gcn, w_ih, w_hh, norm_adj, wgs, wihs, whhs, adjcs);

    // Fused 3-pass GCN + gi GEMM (8 warps, 32x64 tiles)
    gcn_fused<<<NBATCH / 2, 256, GCN_SMEM>>>(inputs, wgs, wihs, adjcs, b_gcn, b_ih, gi);

    // gh GEMM + GRU + fc2
    gemm_gru<<<NROWS / BM, 256, GEMM_SMEM>>>(hidden, whhs, gi, b_hh, w_fc2, b_fc2,
                                             h_out, q_out);
}